// round 12
// baseline (speedup 1.0000x reference)
#include <cuda_runtime.h>
#include <math.h>

#define BB 64
#define FF 240
#define JJ 22
#define NSEG 16
#define NPATH 5
#define WPC 16           // primary frames (= warps) per CTA; FF/WPC = 15 CTAs per row

__constant__ int c_seg_s[NSEG] = {2,5,8,  1,4,7,  3,6,9,12,  14,17,19,  13,16,18};
__constant__ int c_seg_e[NSEG] = {5,8,11, 4,7,10, 6,9,12,15, 17,19,21,  16,18,20};
__constant__ int c_path_off[NPATH] = {0,3,6,10,13};
__constant__ int c_path_cnt[NPATH] = {3,3,4,3,3};

// ---------------- packed f32x2 primitives (sm_103a) ----------------
typedef unsigned long long f2;

__device__ __forceinline__ f2 pk2(float lo, float hi) {
    f2 r; asm("mov.b64 %0, {%1, %2};" : "=l"(r) : "f"(lo), "f"(hi)); return r;
}
__device__ __forceinline__ void upk2(float& lo, float& hi, f2 v) {
    asm("mov.b64 {%0, %1}, %2;" : "=f"(lo), "=f"(hi) : "l"(v));
}
__device__ __forceinline__ f2 bc(float v) {
    unsigned u = __float_as_uint(v);
    return ((f2)u << 32) | (f2)u;
}
__device__ __forceinline__ f2 f2fma(f2 a, f2 b, f2 c) {
    f2 r; asm("fma.rn.f32x2 %0, %1, %2, %3;" : "=l"(r) : "l"(a), "l"(b), "l"(c)); return r;
}
__device__ __forceinline__ f2 f2mul(f2 a, f2 b) {
    f2 r; asm("mul.rn.f32x2 %0, %1, %2;" : "=l"(r) : "l"(a), "l"(b)); return r;
}
__device__ __forceinline__ f2 f2add(f2 a, f2 b) {
    f2 r; asm("add.rn.f32x2 %0, %1, %2;" : "=l"(r) : "l"(a), "l"(b)); return r;
}
__device__ __forceinline__ f2 f2sub(f2 a, f2 b) {
    f2 r; asm("sub.rn.f32x2 %0, %1, %2;" : "=l"(r) : "l"(a), "l"(b)); return r;
}
__device__ __forceinline__ f2 f2abs(f2 a) { return a & 0x7FFFFFFF7FFFFFFFULL; }

struct V3p { f2 x, y, z; };

__device__ __forceinline__ V3p p_sub(V3p a, V3p b) {
    return { f2sub(a.x,b.x), f2sub(a.y,b.y), f2sub(a.z,b.z) };
}
__device__ __forceinline__ V3p p_cross(V3p a, V3p b) {
    return { f2sub(f2mul(a.y, b.z), f2mul(a.z, b.y)),
             f2sub(f2mul(a.z, b.x), f2mul(a.x, b.z)),
             f2sub(f2mul(a.x, b.y), f2mul(a.y, b.x)) };
}
__device__ __forceinline__ f2 p_dot(V3p a, V3p b) {
    return f2fma(a.z, b.z, f2fma(a.y, b.y, f2mul(a.x, b.x)));
}

__device__ __forceinline__ f2 grsqrt2(f2 ss) {
    float l, h; upk2(l, h, ss);
    float rl = fminf(rsqrtf(l), 1e30f);
    float rh = fminf(rsqrtf(h), 1e30f);
    return pk2(rl, rh);
}

// packed asin with built-in saturation (|x|>=1 -> sign(x)*pi/2); replaces clip+asin
__device__ __forceinline__ f2 asin2(f2 x) {
    f2 ax = f2abs(x);
    f2 a2 = f2mul(ax, ax);
    f2 w  = f2fma(ax, bc(-0.5f), bc(0.5f));      // (1-a)/2
    float a2l, a2h, wl, wh, al, ah;
    upk2(a2l, a2h, a2); upk2(wl, wh, w); upk2(al, ah, ax);
    float zl = fminf(a2l, wl), zh = fminf(a2h, wh);   // z<0 iff a>1
    float sl = fmaxf(zl * rsqrtf(zl), 0.0f);          // sqrt(z), NaN/neg -> 0
    float sh = fmaxf(zh * rsqrtf(zh), 0.0f);
    float bl = fminf(fmaxf(fmaf(al, 1e30f, -5e29f), 0.0f), 1.0f);   // a>0.5 ? 1 : 0
    float bh = fminf(fmaxf(fmaf(ah, 1e30f, -5e29f), 0.0f), 1.0f);
    f2 z = pk2(zl, zh);
    f2 s = pk2(sl, sh);
    f2 bg = pk2(bl, bh);
    f2 p = bc(4.2163199048e-2f);
    p = f2fma(p, z, bc(2.4181311049e-2f));
    p = f2fma(p, z, bc(4.5470025998e-2f));
    p = f2fma(p, z, bc(7.4953002686e-2f));
    p = f2fma(p, z, bc(1.6666752422e-1f));
    f2 t = f2fma(f2mul(s, z), p, s);
    f2 v = f2fma(t, bc(-3.0f), bc(1.5707963267948966f));
    f2 r = f2fma(bg, v, t);
    return r | (x & 0x8000000080000000ULL);
}

__device__ __forceinline__ float wmaxf(float v) {
    #pragma unroll
    for (int o = 16; o; o >>= 1) v = fmaxf(v, __shfl_xor_sync(0xffffffffu, v, o));
    return v;
}
__device__ __forceinline__ float wminf(float v) {
    #pragma unroll
    for (int o = 16; o; o >>= 1) v = fminf(v, __shfl_xor_sync(0xffffffffu, v, o));
    return v;
}

// bbox-overlap flag for one global frame, loads straight from gmem (warp-collective)
__device__ __forceinline__ float flag_of_frame(
    const float* __restrict__ motion1, const float* __restrict__ motion2,
    int gf, int lane)
{
    const float* p1 = motion1 + (size_t)gf * 66;
    const float* p2 = motion2 + (size_t)gf * 66;
    bool ok = lane < JJ;
    float x1 = ok ? p1[3*lane]     :  1e30f;
    float z1 = ok ? p1[3*lane + 2] :  1e30f;
    float x2 = ok ? p2[3*lane]     :  1e30f;
    float z2 = ok ? p2[3*lane + 2] :  1e30f;
    float X1 = ok ? x1 : -1e30f, Z1 = ok ? z1 : -1e30f;
    float X2 = ok ? x2 : -1e30f, Z2 = ok ? z2 : -1e30f;
    float nx1 = wminf(x1), xx1 = wmaxf(X1);
    float nz1 = wminf(z1), xz1 = wmaxf(Z1);
    float nx2 = wminf(x2), xx2 = wmaxf(X2);
    float nz2 = wminf(z2), xz2 = wmaxf(Z2);
    bool fl = (xx1 >= nx2) && (xx2 >= nx1) && (xz1 >= nz2) && (xz2 >= nz1);
    return fl ? 1.0f : 0.0f;
}

// Fused kernel: CTA = 16 warps, 16 frames of one batch row (+1 halo pose by warp 0).
// pose+flag -> smem; one __syncthreads; each warp emits one velocity output.
__global__ void __launch_bounds__(WPC * 32) fused_kernel(
    const float* __restrict__ motion1,
    const float* __restrict__ motion2,
    float* __restrict__ out)
{
    const int w    = threadIdx.x >> 5;
    const int lane = threadIdx.x & 31;
    const int b    = blockIdx.x / (FF / WPC);     // batch row
    const int c    = blockIdx.x % (FF / WPC);     // chunk in row, 0..14
    const int f0   = c * WPC;                     // local frame base
    const int row  = b * FF;

    __shared__ float2 jnt[WPC][2][33];
    __shared__ float  gbuf[WPC][256];
    __shared__ float  pose[WPC + 1][32];          // local poses f0 .. f0+16
    __shared__ float  flg[WPC + 3];               // flags for frames f0-1 .. f0+17

    const float INV4PI = 0.07957747154594767f;

    // ---- pose+flag computation for (jslot, pose_slot, flag_slot, global frame) ----
    // pass 1: every warp its frame; pass 2: warp 0 does halo frame f0+16 (c<14)
    #pragma unroll 1
    for (int pass = 0; pass < 2; ++pass) {
        int pslot, fslot, gf;
        if (pass == 0) { pslot = w;   fslot = w + 1;  gf = row + f0 + w; }
        else {
            if (w != 0 || c == (FF / WPC - 1)) break;
            pslot = WPC; fslot = WPC + 1; gf = row + f0 + WPC;
        }

        {   // stage joints (float2; element 32 by lane 0)
            const float2* p1 = (const float2*)motion1 + (size_t)gf * 33;
            const float2* p2 = (const float2*)motion2 + (size_t)gf * 33;
            jnt[w][0][lane] = p1[lane];
            jnt[w][1][lane] = p2[lane];
            if (lane == 0) { jnt[w][0][32] = p1[32]; jnt[w][1][32] = p2[32]; }
        }
        __syncwarp();

        const float* m1s = (const float*)jnt[w][0];
        const float* m2s = (const float*)jnt[w][1];

        // bbox flag from staged smem
        {
            bool ok = lane < JJ;
            float x1 = ok ? m1s[3*lane]     :  1e30f;
            float z1 = ok ? m1s[3*lane + 2] :  1e30f;
            float x2 = ok ? m2s[3*lane]     :  1e30f;
            float z2 = ok ? m2s[3*lane + 2] :  1e30f;
            float X1 = ok ? x1 : -1e30f, Z1 = ok ? z1 : -1e30f;
            float X2 = ok ? x2 : -1e30f, Z2 = ok ? z2 : -1e30f;
            float nx1 = wminf(x1), xx1 = wmaxf(X1);
            float nz1 = wminf(z1), xz1 = wmaxf(Z1);
            float nx2 = wminf(x2), xx2 = wmaxf(X2);
            float nz2 = wminf(z2), xz2 = wmaxf(Z2);
            if (lane == 0) {
                bool fl = (xx1 >= nx2) && (xx2 >= nx1) && (xz1 >= nz2) && (xz2 >= nz1);
                flg[fslot] = fl ? 1.0f : 0.0f;
            }
        }

        // packed GLI: lane covers n = lane&15; m pairs (2i+h, 2i+h+8)
        const int n = lane & 15;
        const int h = lane >> 4;
        const int js2 = 3 * c_seg_s[n], je2 = 3 * c_seg_e[n];
        const V3p s2p = { bc(m2s[js2]), bc(m2s[js2+1]), bc(m2s[js2+2]) };
        const V3p e2p = { bc(m2s[je2]), bc(m2s[je2+1]), bc(m2s[je2+2]) };

        #pragma unroll 2
        for (int i = 0; i < 4; ++i) {
            const int mlo = 2 * i + h;
            const int mhi = mlo + 8;
            const int sa = 3 * c_seg_s[mlo], sb = 3 * c_seg_s[mhi];
            const int ea = 3 * c_seg_e[mlo], eb = 3 * c_seg_e[mhi];
            V3p s1p = { pk2(m1s[sa], m1s[sb]), pk2(m1s[sa+1], m1s[sb+1]), pk2(m1s[sa+2], m1s[sb+2]) };
            V3p e1p = { pk2(m1s[ea], m1s[eb]), pk2(m1s[ea+1], m1s[eb+1]), pk2(m1s[ea+2], m1s[eb+2]) };

            V3p r13 = p_sub(s2p, s1p);
            V3p r14 = p_sub(e2p, s1p);
            V3p r12 = p_sub(e1p, s1p);

            V3p A  = p_cross(r13, r14);
            V3p Bv = p_cross(r12, r14);
            V3p Cv = p_cross(r12, r13);

            f2 gAA = p_dot(A, A);
            f2 gBB = p_dot(Bv, Bv);
            f2 gCC = p_dot(Cv, Cv);
            f2 gAB = p_dot(A, Bv);
            f2 gBC = p_dot(Bv, Cv);
            f2 gCA = p_dot(Cv, A);

            f2 ss2 = f2add(f2add(gAA, gBB), gCC);
            ss2 = f2fma(gAB, bc(-2.0f), ss2);
            ss2 = f2fma(gBC, bc(-2.0f), ss2);
            ss2 = f2fma(gCA, bc( 2.0f), ss2);

            f2 n12 = f2sub(f2sub(gBB, gAB), gBC);
            f2 n23 = f2sub(f2sub(gBC, gCA), gCC);

            f2 r0 = grsqrt2(gAA);
            f2 r1 = grsqrt2(gBB);
            f2 r2 = grsqrt2(ss2);
            f2 r3 = grsqrt2(gCC);

            f2 d01 = f2mul(f2mul(gAB, r0), r1);
            f2 d12 = f2mul(f2mul(n12, r1), r2);
            f2 d23 = f2mul(f2mul(n23, r2), r3);
            f2 d30 = f2mul(f2mul(gCA, r3), r0);
            f2 tot = f2sub(f2add(asin2(d01), asin2(d12)),
                           f2add(asin2(d23), asin2(d30)));
            tot = f2mul(tot, bc(INV4PI));

            f2 sgB = p_dot(Bv, r13);              // = -sign

            float sgl, sgh, totl, toth;
            upk2(sgl, sgh, sgB); upk2(totl, toth, tot);
            gbuf[w][mlo * 16 + n] = (sgl >= 0.0f) ? -totl : totl;
            gbuf[w][mhi * 16 + n] = (sgh >= 0.0f) ? -toth : toth;
        }
        __syncwarp();

        if (lane < 25) {
            const int pi = lane / 5;
            const int pj = lane % 5;
            const int mo = c_path_off[pi], mc = c_path_cnt[pi];
            const int no = c_path_off[pj], nc = c_path_cnt[pj];
            float s = 0.0f;
            for (int m = mo; m < mo + mc; ++m)
                for (int nn = no; nn < no + nc; ++nn)
                    s += gbuf[w][m * 16 + nn];
            pose[pslot][lane] = s;
        }
        __syncwarp();
    }

    // boundary flags (each slot has exactly one writer; invalid -> 0)
    if (w == 1) {
        float v = (c > 0) ? flag_of_frame(motion1, motion2, row + f0 - 1, lane) : 0.0f;
        if (lane == 0) flg[0] = v;
    }
    if (w == 2) {
        float v = (f0 + WPC + 1 < FF) ? flag_of_frame(motion1, motion2, row + f0 + WPC + 1, lane) : 0.0f;
        if (lane == 0) flg[WPC + 2] = v;
    }
    if (w == 3 && c == (FF / WPC - 1) && lane == 0) flg[WPC + 1] = 0.0f;  // frame 240 pad

    __syncthreads();

    // ---- velocity output: warp w -> f = f0 + w ----
    const int f = f0 + w;
    if (f < FF - 1) {
        float m0 = (flg[w]   != 0.0f || flg[w+1] != 0.0f || flg[w+2] != 0.0f) ? 1.0f : 0.0f;
        float m1 = (flg[w+1] != 0.0f || flg[w+2] != 0.0f || flg[w+3] != 0.0f) ? 1.0f : 0.0f;
        float d = 0.0f;
        if (lane < 25) {
            d = fabsf(pose[w + 1][lane] * m1 - pose[w][lane] * m0);
        }
        d = wmaxf(d);
        if (lane == 0) out[b * (FF - 1) + f] = d;
    }
}

extern "C" void kernel_launch(void* const* d_in, const int* in_sizes, int n_in,
                              void* d_out, int out_size)
{
    const float* motion1 = (const float*)d_in[0];
    const float* motion2 = (const float*)d_in[1];
    float* out = (float*)d_out;

    fused_kernel<<<BB * (FF / WPC), WPC * 32>>>(motion1, motion2, out);
}

// round 13
// speedup vs baseline: 1.2962x; 1.2962x over previous
#include <cuda_runtime.h>
#include <math.h>

#define BB 64
#define FF 240
#define JJ 22
#define NSEG 16
#define NPATH 5
#define NW 16            // warps per CTA = poses per CTA; outputs per CTA = 15
#define OPC 15           // outputs per chunk
#define CPR 16           // chunks per row (16*15 = 240 >= 239 outputs)

__constant__ int c_seg_s[NSEG] = {2,5,8,  1,4,7,  3,6,9,12,  14,17,19,  13,16,18};
__constant__ int c_seg_e[NSEG] = {5,8,11, 4,7,10, 6,9,12,15, 17,19,21,  16,18,20};
__constant__ int c_path_off[NPATH] = {0,3,6,10,13};
__constant__ int c_path_cnt[NPATH] = {3,3,4,3,3};

// ---------------- packed f32x2 primitives (sm_103a) ----------------
typedef unsigned long long f2;

__device__ __forceinline__ f2 pk2(float lo, float hi) {
    f2 r; asm("mov.b64 %0, {%1, %2};" : "=l"(r) : "f"(lo), "f"(hi)); return r;
}
__device__ __forceinline__ void upk2(float& lo, float& hi, f2 v) {
    asm("mov.b64 {%0, %1}, %2;" : "=f"(lo), "=f"(hi) : "l"(v));
}
__device__ __forceinline__ f2 bc(float v) {
    unsigned u = __float_as_uint(v);
    return ((f2)u << 32) | (f2)u;
}
__device__ __forceinline__ f2 f2fma(f2 a, f2 b, f2 c) {
    f2 r; asm("fma.rn.f32x2 %0, %1, %2, %3;" : "=l"(r) : "l"(a), "l"(b), "l"(c)); return r;
}
__device__ __forceinline__ f2 f2mul(f2 a, f2 b) {
    f2 r; asm("mul.rn.f32x2 %0, %1, %2;" : "=l"(r) : "l"(a), "l"(b)); return r;
}
__device__ __forceinline__ f2 f2add(f2 a, f2 b) {
    f2 r; asm("add.rn.f32x2 %0, %1, %2;" : "=l"(r) : "l"(a), "l"(b)); return r;
}
__device__ __forceinline__ f2 f2sub(f2 a, f2 b) {
    f2 r; asm("sub.rn.f32x2 %0, %1, %2;" : "=l"(r) : "l"(a), "l"(b)); return r;
}
__device__ __forceinline__ f2 f2abs(f2 a) { return a & 0x7FFFFFFF7FFFFFFFULL; }

struct V3p { f2 x, y, z; };

__device__ __forceinline__ V3p p_sub(V3p a, V3p b) {
    return { f2sub(a.x,b.x), f2sub(a.y,b.y), f2sub(a.z,b.z) };
}
__device__ __forceinline__ V3p p_cross(V3p a, V3p b) {
    return { f2sub(f2mul(a.y, b.z), f2mul(a.z, b.y)),
             f2sub(f2mul(a.z, b.x), f2mul(a.x, b.z)),
             f2sub(f2mul(a.x, b.y), f2mul(a.y, b.x)) };
}
__device__ __forceinline__ f2 p_dot(V3p a, V3p b) {
    return f2fma(a.z, b.z, f2fma(a.y, b.y, f2mul(a.x, b.x)));
}

__device__ __forceinline__ f2 grsqrt2(f2 ss) {
    float l, h; upk2(l, h, ss);
    float rl = fminf(rsqrtf(l), 1e30f);
    float rh = fminf(rsqrtf(h), 1e30f);
    return pk2(rl, rh);
}

// packed asin with built-in saturation (|x|>=1 -> sign(x)*pi/2); replaces clip+asin
__device__ __forceinline__ f2 asin2(f2 x) {
    f2 ax = f2abs(x);
    f2 a2 = f2mul(ax, ax);
    f2 w  = f2fma(ax, bc(-0.5f), bc(0.5f));      // (1-a)/2
    float a2l, a2h, wl, wh, al, ah;
    upk2(a2l, a2h, a2); upk2(wl, wh, w); upk2(al, ah, ax);
    float zl = fminf(a2l, wl), zh = fminf(a2h, wh);   // z<0 iff a>1
    float sl = fmaxf(zl * rsqrtf(zl), 0.0f);          // sqrt(z), NaN/neg -> 0
    float sh = fmaxf(zh * rsqrtf(zh), 0.0f);
    float bl = fminf(fmaxf(fmaf(al, 1e30f, -5e29f), 0.0f), 1.0f);   // a>0.5 ? 1 : 0
    float bh = fminf(fmaxf(fmaf(ah, 1e30f, -5e29f), 0.0f), 1.0f);
    f2 z = pk2(zl, zh);
    f2 s = pk2(sl, sh);
    f2 bg = pk2(bl, bh);
    f2 p = bc(4.2163199048e-2f);
    p = f2fma(p, z, bc(2.4181311049e-2f));
    p = f2fma(p, z, bc(4.5470025998e-2f));
    p = f2fma(p, z, bc(7.4953002686e-2f));
    p = f2fma(p, z, bc(1.6666752422e-1f));
    f2 t = f2fma(f2mul(s, z), p, s);
    f2 v = f2fma(t, bc(-3.0f), bc(1.5707963267948966f));
    f2 r = f2fma(bg, v, t);
    return r | (x & 0x8000000080000000ULL);
}

__device__ __forceinline__ float wmaxf(float v) {
    #pragma unroll
    for (int o = 16; o; o >>= 1) v = fmaxf(v, __shfl_xor_sync(0xffffffffu, v, o));
    return v;
}
__device__ __forceinline__ float wminf(float v) {
    #pragma unroll
    for (int o = 16; o; o >>= 1) v = fminf(v, __shfl_xor_sync(0xffffffffu, v, o));
    return v;
}

// bbox-overlap flag for one global frame, straight from gmem (warp-collective)
__device__ __forceinline__ float flag_of_frame(
    const float* __restrict__ motion1, const float* __restrict__ motion2,
    int gf, int lane)
{
    const float* p1 = motion1 + (size_t)gf * 66;
    const float* p2 = motion2 + (size_t)gf * 66;
    bool ok = lane < JJ;
    float x1 = ok ? p1[3*lane]     :  1e30f;
    float z1 = ok ? p1[3*lane + 2] :  1e30f;
    float x2 = ok ? p2[3*lane]     :  1e30f;
    float z2 = ok ? p2[3*lane + 2] :  1e30f;
    float X1 = ok ? x1 : -1e30f, Z1 = ok ? z1 : -1e30f;
    float X2 = ok ? x2 : -1e30f, Z2 = ok ? z2 : -1e30f;
    float nx1 = wminf(x1), xx1 = wmaxf(X1);
    float nz1 = wminf(z1), xz1 = wmaxf(Z1);
    float nx2 = wminf(x2), xx2 = wmaxf(X2);
    float nz2 = wminf(z2), xz2 = wmaxf(Z2);
    bool fl = (xx1 >= nx2) && (xx2 >= nx1) && (xz1 >= nz2) && (xz2 >= nz1);
    return fl ? 1.0f : 0.0f;
}

// Fused: CTA = 16 warps = 16 poses (frames f0..f0+15), 15 outputs (f0..f0+14).
// Exactly ONE pose per warp — no serial halo. One __syncthreads, vel from smem.
__global__ void __launch_bounds__(NW * 32) fused_kernel(
    const float* __restrict__ motion1,
    const float* __restrict__ motion2,
    float* __restrict__ out)
{
    const int w    = threadIdx.x >> 5;
    const int lane = threadIdx.x & 31;
    const int b    = blockIdx.x / CPR;            // batch row
    const int c    = blockIdx.x % CPR;            // chunk in row
    const int f0   = c * OPC;                     // first output frame
    const int row  = b * FF;

    __shared__ float2 jnt[NW][2][33];
    __shared__ float  gbuf[NW][256];
    __shared__ float  pose[NW][32];               // poses for frames f0+0 .. f0+15
    __shared__ float  flg[NW + 2];                // flags for frames f0-1 .. f0+16

    const float INV4PI = 0.07957747154594767f;

    // ---- each warp: one pose (frame f0+w) + its flag ----
    const int  pf     = f0 + w;                   // local pose frame
    const bool pvalid = pf < FF;                  // only false for c=15,w=15
    const int  gf     = row + (pvalid ? pf : FF - 1);   // clamp (pose unused then)

    {   // stage joints (float2; element 32 by lane 0)
        const float2* p1 = (const float2*)motion1 + (size_t)gf * 33;
        const float2* p2 = (const float2*)motion2 + (size_t)gf * 33;
        jnt[w][0][lane] = p1[lane];
        jnt[w][1][lane] = p2[lane];
        if (lane == 0) { jnt[w][0][32] = p1[32]; jnt[w][1][32] = p2[32]; }
    }
    __syncwarp();

    const float* m1s = (const float*)jnt[w][0];
    const float* m2s = (const float*)jnt[w][1];

    // bbox flag from staged smem -> slot w+1 (frame f0+w)
    {
        bool ok = lane < JJ;
        float x1 = ok ? m1s[3*lane]     :  1e30f;
        float z1 = ok ? m1s[3*lane + 2] :  1e30f;
        float x2 = ok ? m2s[3*lane]     :  1e30f;
        float z2 = ok ? m2s[3*lane + 2] :  1e30f;
        float X1 = ok ? x1 : -1e30f, Z1 = ok ? z1 : -1e30f;
        float X2 = ok ? x2 : -1e30f, Z2 = ok ? z2 : -1e30f;
        float nx1 = wminf(x1), xx1 = wmaxf(X1);
        float nz1 = wminf(z1), xz1 = wmaxf(Z1);
        float nx2 = wminf(x2), xx2 = wmaxf(X2);
        float nz2 = wminf(z2), xz2 = wmaxf(Z2);
        if (lane == 0) {
            bool fl = (xx1 >= nx2) && (xx2 >= nx1) && (xz1 >= nz2) && (xz2 >= nz1);
            flg[w + 1] = (fl && pvalid) ? 1.0f : 0.0f;
        }
    }

    // boundary flags: slot 0 = frame f0-1 (warp 0), slot 17 = frame f0+16 (warp 1)
    if (w == 0) {
        float v = (c > 0) ? flag_of_frame(motion1, motion2, row + f0 - 1, lane) : 0.0f;
        if (lane == 0) flg[0] = v;
    }
    if (w == 1) {
        int hf = f0 + NW;
        float v = (hf < FF) ? flag_of_frame(motion1, motion2, row + hf, lane) : 0.0f;
        if (lane == 0) flg[NW + 1] = v;
    }

    // ---- packed GLI: lane covers n = lane&15; m pairs (2i+h, 2i+h+8) ----
    const int n = lane & 15;
    const int h = lane >> 4;
    const int js2 = 3 * c_seg_s[n], je2 = 3 * c_seg_e[n];
    const V3p s2p = { bc(m2s[js2]), bc(m2s[js2+1]), bc(m2s[js2+2]) };
    const V3p e2p = { bc(m2s[je2]), bc(m2s[je2+1]), bc(m2s[je2+2]) };

    #pragma unroll 2
    for (int i = 0; i < 4; ++i) {
        const int mlo = 2 * i + h;
        const int mhi = mlo + 8;
        const int sa = 3 * c_seg_s[mlo], sb = 3 * c_seg_s[mhi];
        const int ea = 3 * c_seg_e[mlo], eb = 3 * c_seg_e[mhi];
        V3p s1p = { pk2(m1s[sa], m1s[sb]), pk2(m1s[sa+1], m1s[sb+1]), pk2(m1s[sa+2], m1s[sb+2]) };
        V3p e1p = { pk2(m1s[ea], m1s[eb]), pk2(m1s[ea+1], m1s[eb+1]), pk2(m1s[ea+2], m1s[eb+2]) };

        V3p r13 = p_sub(s2p, s1p);
        V3p r14 = p_sub(e2p, s1p);
        V3p r12 = p_sub(e1p, s1p);

        V3p A  = p_cross(r13, r14);
        V3p Bv = p_cross(r12, r14);
        V3p Cv = p_cross(r12, r13);

        f2 gAA = p_dot(A, A);
        f2 gBB = p_dot(Bv, Bv);
        f2 gCC = p_dot(Cv, Cv);
        f2 gAB = p_dot(A, Bv);
        f2 gBC = p_dot(Bv, Cv);
        f2 gCA = p_dot(Cv, A);

        f2 ss2 = f2add(f2add(gAA, gBB), gCC);
        ss2 = f2fma(gAB, bc(-2.0f), ss2);
        ss2 = f2fma(gBC, bc(-2.0f), ss2);
        ss2 = f2fma(gCA, bc( 2.0f), ss2);

        f2 n12 = f2sub(f2sub(gBB, gAB), gBC);
        f2 n23 = f2sub(f2sub(gBC, gCA), gCC);

        f2 r0 = grsqrt2(gAA);
        f2 r1 = grsqrt2(gBB);
        f2 r2 = grsqrt2(ss2);
        f2 r3 = grsqrt2(gCC);

        f2 d01 = f2mul(f2mul(gAB, r0), r1);
        f2 d12 = f2mul(f2mul(n12, r1), r2);
        f2 d23 = f2mul(f2mul(n23, r2), r3);
        f2 d30 = f2mul(f2mul(gCA, r3), r0);
        f2 tot = f2sub(f2add(asin2(d01), asin2(d12)),
                       f2add(asin2(d23), asin2(d30)));
        tot = f2mul(tot, bc(INV4PI));

        f2 sgB = p_dot(Bv, r13);              // = -sign

        float sgl, sgh, totl, toth;
        upk2(sgl, sgh, sgB); upk2(totl, toth, tot);
        gbuf[w][mlo * 16 + n] = (sgl >= 0.0f) ? -totl : totl;
        gbuf[w][mhi * 16 + n] = (sgh >= 0.0f) ? -toth : toth;
    }
    __syncwarp();

    if (lane < 25) {
        const int pi = lane / 5;
        const int pj = lane % 5;
        const int mo = c_path_off[pi], mc = c_path_cnt[pi];
        const int no = c_path_off[pj], nc = c_path_cnt[pj];
        float s = 0.0f;
        for (int m = mo; m < mo + mc; ++m)
            for (int nn = no; nn < no + nc; ++nn)
                s += gbuf[w][m * 16 + nn];
        pose[w][lane] = s;
    }

    __syncthreads();

    // ---- velocity output: warp w -> f = f0 + w (needs pose[w], pose[w+1]) ----
    const int f = f0 + w;
    if (w < OPC && f < FF - 1) {
        float m0 = (flg[w]   != 0.0f || flg[w+1] != 0.0f || flg[w+2] != 0.0f) ? 1.0f : 0.0f;
        float m1 = (flg[w+1] != 0.0f || flg[w+2] != 0.0f || flg[w+3] != 0.0f) ? 1.0f : 0.0f;
        float d = 0.0f;
        if (lane < 25) {
            d = fabsf(pose[w + 1][lane] * m1 - pose[w][lane] * m0);
        }
        d = wmaxf(d);
        if (lane == 0) out[b * (FF - 1) + f] = d;
    }
}

extern "C" void kernel_launch(void* const* d_in, const int* in_sizes, int n_in,
                              void* d_out, int out_size)
{
    const float* motion1 = (const float*)d_in[0];
    const float* motion2 = (const float*)d_in[1];
    float* out = (float*)d_out;

    fused_kernel<<<BB * CPR, NW * 32>>>(motion1, motion2, out);
}

// round 14
// speedup vs baseline: 1.3057x; 1.0073x over previous
#include <cuda_runtime.h>
#include <math.h>

#define BB 64
#define FF 240
#define JJ 22
#define NSEG 16
#define NPATH 5
#define NW 16            // warps per CTA = poses per CTA; outputs per CTA = 15
#define OPC 15           // outputs per chunk
#define CPR 16           // chunks per row

__constant__ int c_seg_s[NSEG] = {2,5,8,  1,4,7,  3,6,9,12,  14,17,19,  13,16,18};
__constant__ int c_seg_e[NSEG] = {5,8,11, 4,7,10, 6,9,12,15, 17,19,21,  16,18,20};
__constant__ int c_path_off[NPATH] = {0,3,6,10,13};
__constant__ int c_path_cnt[NPATH] = {3,3,4,3,3};

// ---------------- packed f32x2 primitives (sm_103a) ----------------
typedef unsigned long long f2;

__device__ __forceinline__ f2 pk2(float lo, float hi) {
    f2 r; asm("mov.b64 %0, {%1, %2};" : "=l"(r) : "f"(lo), "f"(hi)); return r;
}
__device__ __forceinline__ void upk2(float& lo, float& hi, f2 v) {
    asm("mov.b64 {%0, %1}, %2;" : "=f"(lo), "=f"(hi) : "l"(v));
}
__device__ __forceinline__ f2 bc(float v) {
    unsigned u = __float_as_uint(v);
    return ((f2)u << 32) | (f2)u;
}
__device__ __forceinline__ f2 f2fma(f2 a, f2 b, f2 c) {
    f2 r; asm("fma.rn.f32x2 %0, %1, %2, %3;" : "=l"(r) : "l"(a), "l"(b), "l"(c)); return r;
}
__device__ __forceinline__ f2 f2mul(f2 a, f2 b) {
    f2 r; asm("mul.rn.f32x2 %0, %1, %2;" : "=l"(r) : "l"(a), "l"(b)); return r;
}
__device__ __forceinline__ f2 f2add(f2 a, f2 b) {
    f2 r; asm("add.rn.f32x2 %0, %1, %2;" : "=l"(r) : "l"(a), "l"(b)); return r;
}
__device__ __forceinline__ f2 f2sub(f2 a, f2 b) {
    f2 r; asm("sub.rn.f32x2 %0, %1, %2;" : "=l"(r) : "l"(a), "l"(b)); return r;
}
__device__ __forceinline__ f2 f2abs(f2 a) { return a & 0x7FFFFFFF7FFFFFFFULL; }

struct V3p { f2 x, y, z; };

__device__ __forceinline__ V3p p_sub(V3p a, V3p b) {
    return { f2sub(a.x,b.x), f2sub(a.y,b.y), f2sub(a.z,b.z) };
}
__device__ __forceinline__ V3p p_cross(V3p a, V3p b) {
    return { f2sub(f2mul(a.y, b.z), f2mul(a.z, b.y)),
             f2sub(f2mul(a.z, b.x), f2mul(a.x, b.z)),
             f2sub(f2mul(a.x, b.y), f2mul(a.y, b.x)) };
}
__device__ __forceinline__ f2 p_dot(V3p a, V3p b) {
    return f2fma(a.z, b.z, f2fma(a.y, b.y, f2mul(a.x, b.x)));
}

__device__ __forceinline__ f2 grsqrt2(f2 ss) {
    float l, h; upk2(l, h, ss);
    float rl = fminf(rsqrtf(l), 1e30f);
    float rh = fminf(rsqrtf(h), 1e30f);
    return pk2(rl, rh);
}

// A&S 4.4.46 packed asin: asin(a) = pi/2 - sqrt(1-a)*P7(a), a=|x| in [0,1],
// |eps|<=2e-8. Saturates for |x|>1 (1-a<0 -> NaN -> 0 -> pi/2) = clip+asin.
// No range split, no selects, no blends.
__device__ __forceinline__ f2 asin2(f2 x) {
    f2 ax = f2abs(x);
    f2 w  = f2sub(bc(1.0f), ax);
    float wl, wh; upk2(wl, wh, w);
    float sl = fmaxf(wl * rsqrtf(wl), 0.0f);   // sqrt(w); w<=0 -> 0
    float sh = fmaxf(wh * rsqrtf(wh), 0.0f);
    f2 s = pk2(sl, sh);
    f2 p = bc(-1.2624911e-3f);
    p = f2fma(p, ax, bc( 6.6700901e-3f));
    p = f2fma(p, ax, bc(-1.70881256e-2f));
    p = f2fma(p, ax, bc( 3.08918810e-2f));
    p = f2fma(p, ax, bc(-5.01743046e-2f));
    p = f2fma(p, ax, bc( 8.89789874e-2f));
    p = f2fma(p, ax, bc(-2.145988016e-1f));
    p = f2fma(p, ax, bc( 1.5707963050f));
    f2 r = f2sub(bc(1.5707963267948966f), f2mul(s, p));   // >= 0
    return r | (x & 0x8000000080000000ULL);                // apply sign(x)
}

__device__ __forceinline__ float wmaxf(float v) {
    #pragma unroll
    for (int o = 16; o; o >>= 1) v = fmaxf(v, __shfl_xor_sync(0xffffffffu, v, o));
    return v;
}
__device__ __forceinline__ float wminf(float v) {
    #pragma unroll
    for (int o = 16; o; o >>= 1) v = fminf(v, __shfl_xor_sync(0xffffffffu, v, o));
    return v;
}

// bbox-overlap flag for one global frame, straight from gmem (warp-collective)
__device__ __forceinline__ float flag_of_frame(
    const float* __restrict__ motion1, const float* __restrict__ motion2,
    int gf, int lane)
{
    const float* p1 = motion1 + (size_t)gf * 66;
    const float* p2 = motion2 + (size_t)gf * 66;
    bool ok = lane < JJ;
    float x1 = ok ? p1[3*lane]     :  1e30f;
    float z1 = ok ? p1[3*lane + 2] :  1e30f;
    float x2 = ok ? p2[3*lane]     :  1e30f;
    float z2 = ok ? p2[3*lane + 2] :  1e30f;
    float X1 = ok ? x1 : -1e30f, Z1 = ok ? z1 : -1e30f;
    float X2 = ok ? x2 : -1e30f, Z2 = ok ? z2 : -1e30f;
    float nx1 = wminf(x1), xx1 = wmaxf(X1);
    float nz1 = wminf(z1), xz1 = wmaxf(Z1);
    float nx2 = wminf(x2), xx2 = wmaxf(X2);
    float nz2 = wminf(z2), xz2 = wmaxf(Z2);
    bool fl = (xx1 >= nx2) && (xx2 >= nx1) && (xz1 >= nz2) && (xz2 >= nz1);
    return fl ? 1.0f : 0.0f;
}

// Fused: CTA = 16 warps = 16 poses (frames f0..f0+15), 15 outputs (f0..f0+14).
__global__ void __launch_bounds__(NW * 32) fused_kernel(
    const float* __restrict__ motion1,
    const float* __restrict__ motion2,
    float* __restrict__ out)
{
    const int w    = threadIdx.x >> 5;
    const int lane = threadIdx.x & 31;
    const int b    = blockIdx.x / CPR;
    const int c    = blockIdx.x % CPR;
    const int f0   = c * OPC;
    const int row  = b * FF;

    __shared__ float2 jnt[NW][2][33];
    __shared__ f2     pkj[NW][48];     // prepacked m1 endpoints: [mlo*6 + pt*3 + c]
    __shared__ float  gbuf[NW][256];
    __shared__ float  pose[NW][32];
    __shared__ float  flg[NW + 2];     // flags for frames f0-1 .. f0+16

    const float INV4PI = 0.07957747154594767f;

    const int  pf     = f0 + w;
    const bool pvalid = pf < FF;                       // only false for c=15,w=15
    const int  gf     = row + (pvalid ? pf : FF - 1);  // clamp (pose unused then)

    {   // stage joints (float2; element 32 by lane 0)
        const float2* p1 = (const float2*)motion1 + (size_t)gf * 33;
        const float2* p2 = (const float2*)motion2 + (size_t)gf * 33;
        jnt[w][0][lane] = p1[lane];
        jnt[w][1][lane] = p2[lane];
        if (lane == 0) { jnt[w][0][32] = p1[32]; jnt[w][1][32] = p2[32]; }
    }
    __syncwarp();

    const float* m1s = (const float*)jnt[w][0];
    const float* m2s = (const float*)jnt[w][1];

    // prepack m1 segment endpoints as f2 pairs (mlo with mlo+8) -> LDS.64 in loop
    {
        #pragma unroll
        for (int l = lane; l < 48; l += 32) {
            int cc   = l % 3;
            int rest = l / 3;        // 0..15
            int pt   = rest & 1;
            int mlo  = rest >> 1;    // 0..7
            int jlo  = pt ? c_seg_e[mlo]     : c_seg_s[mlo];
            int jhi  = pt ? c_seg_e[mlo + 8] : c_seg_s[mlo + 8];
            pkj[w][l] = pk2(m1s[3*jlo + cc], m1s[3*jhi + cc]);
        }
    }

    // bbox flag from staged smem -> slot w+1 (frame f0+w)
    {
        bool ok = lane < JJ;
        float x1 = ok ? m1s[3*lane]     :  1e30f;
        float z1 = ok ? m1s[3*lane + 2] :  1e30f;
        float x2 = ok ? m2s[3*lane]     :  1e30f;
        float z2 = ok ? m2s[3*lane + 2] :  1e30f;
        float X1 = ok ? x1 : -1e30f, Z1 = ok ? z1 : -1e30f;
        float X2 = ok ? x2 : -1e30f, Z2 = ok ? z2 : -1e30f;
        float nx1 = wminf(x1), xx1 = wmaxf(X1);
        float nz1 = wminf(z1), xz1 = wmaxf(Z1);
        float nx2 = wminf(x2), xx2 = wmaxf(X2);
        float nz2 = wminf(z2), xz2 = wmaxf(Z2);
        if (lane == 0) {
            bool fl = (xx1 >= nx2) && (xx2 >= nx1) && (xz1 >= nz2) && (xz2 >= nz1);
            flg[w + 1] = (fl && pvalid) ? 1.0f : 0.0f;
        }
    }

    // boundary flags: slot 0 = frame f0-1 (warp 0), slot 17 = frame f0+16 (warp 1)
    if (w == 0) {
        float v = (c > 0) ? flag_of_frame(motion1, motion2, row + f0 - 1, lane) : 0.0f;
        if (lane == 0) flg[0] = v;
    }
    if (w == 1) {
        int hf = f0 + NW;
        float v = (hf < FF) ? flag_of_frame(motion1, motion2, row + hf, lane) : 0.0f;
        if (lane == 0) flg[NW + 1] = v;
    }
    __syncwarp();

    // ---- packed GLI: lane covers n = lane&15; m pairs (2i+h, 2i+h+8) ----
    const int n = lane & 15;
    const int h = lane >> 4;
    const int js2 = 3 * c_seg_s[n], je2 = 3 * c_seg_e[n];
    const V3p s2p = { bc(m2s[js2]), bc(m2s[js2+1]), bc(m2s[js2+2]) };
    const V3p e2p = { bc(m2s[je2]), bc(m2s[je2+1]), bc(m2s[je2+2]) };
    const f2* pj = &pkj[w][0];

    #pragma unroll 2
    for (int i = 0; i < 4; ++i) {
        const int mlo = 2 * i + h;
        const int base = mlo * 6;
        V3p s1p = { pj[base+0], pj[base+1], pj[base+2] };   // LDS.64, broadcast
        V3p e1p = { pj[base+3], pj[base+4], pj[base+5] };

        V3p r13 = p_sub(s2p, s1p);
        V3p r14 = p_sub(e2p, s1p);
        V3p r12 = p_sub(e1p, s1p);

        V3p A  = p_cross(r13, r14);
        V3p Bv = p_cross(r12, r14);
        V3p Cv = p_cross(r12, r13);

        f2 gAA = p_dot(A, A);
        f2 gBB = p_dot(Bv, Bv);
        f2 gCC = p_dot(Cv, Cv);
        f2 gAB = p_dot(A, Bv);
        f2 gBC = p_dot(Bv, Cv);
        f2 gCA = p_dot(Cv, A);

        f2 ss2 = f2add(f2add(gAA, gBB), gCC);
        ss2 = f2fma(gAB, bc(-2.0f), ss2);
        ss2 = f2fma(gBC, bc(-2.0f), ss2);
        ss2 = f2fma(gCA, bc( 2.0f), ss2);

        f2 n12 = f2sub(f2sub(gBB, gAB), gBC);
        f2 n23 = f2sub(f2sub(gBC, gCA), gCC);

        f2 r0 = grsqrt2(gAA);
        f2 r1 = grsqrt2(gBB);
        f2 r2 = grsqrt2(ss2);
        f2 r3 = grsqrt2(gCC);

        f2 d01 = f2mul(f2mul(gAB, r0), r1);
        f2 d12 = f2mul(f2mul(n12, r1), r2);
        f2 d23 = f2mul(f2mul(n23, r2), r3);
        f2 d30 = f2mul(f2mul(gCA, r3), r0);
        f2 tot = f2sub(f2add(asin2(d01), asin2(d12)),
                       f2add(asin2(d23), asin2(d30)));
        tot = f2mul(tot, bc(INV4PI));

        f2 sgB = p_dot(Bv, r13);              // = -sign

        float sgl, sgh, totl, toth;
        upk2(sgl, sgh, sgB); upk2(totl, toth, tot);
        gbuf[w][(mlo)     * 16 + n] = (sgl >= 0.0f) ? -totl : totl;
        gbuf[w][(mlo + 8) * 16 + n] = (sgh >= 0.0f) ? -toth : toth;
    }
    __syncwarp();

    if (lane < 25) {
        const int pi = lane / 5;
        const int pj2 = lane % 5;
        const int mo = c_path_off[pi], mc = c_path_cnt[pi];
        const int no = c_path_off[pj2], nc = c_path_cnt[pj2];
        float s = 0.0f;
        for (int m = mo; m < mo + mc; ++m)
            for (int nn = no; nn < no + nc; ++nn)
                s += gbuf[w][m * 16 + nn];
        pose[w][lane] = s;
    }

    __syncthreads();

    // ---- velocity output: warp w -> f = f0 + w (needs pose[w], pose[w+1]) ----
    const int f = f0 + w;
    if (w < OPC && f < FF - 1) {
        float m0 = (flg[w]   != 0.0f || flg[w+1] != 0.0f || flg[w+2] != 0.0f) ? 1.0f : 0.0f;
        float m1 = (flg[w+1] != 0.0f || flg[w+2] != 0.0f || flg[w+3] != 0.0f) ? 1.0f : 0.0f;
        float d = 0.0f;
        if (lane < 25) {
            d = fabsf(pose[w + 1][lane] * m1 - pose[w][lane] * m0);
        }
        d = wmaxf(d);
        if (lane == 0) out[b * (FF - 1) + f] = d;
    }
}

extern "C" void kernel_launch(void* const* d_in, const int* in_sizes, int n_in,
                              void* d_out, int out_size)
{
    const float* motion1 = (const float*)d_in[0];
    const float* motion2 = (const float*)d_in[1];
    float* out = (float*)d_out;

    fused_kernel<<<BB * CPR, NW * 32>>>(motion1, motion2, out);
}

// round 15
// speedup vs baseline: 1.3760x; 1.0538x over previous
#include <cuda_runtime.h>
#include <math.h>

#define BB 64
#define FF 240
#define JJ 22
#define NSEG 16
#define NPATH 5
#define NW 16            // warps per CTA = poses per CTA; outputs per CTA = 15
#define OPC 15           // outputs per chunk
#define CPR 16           // chunks per row

__constant__ int c_seg_s[NSEG] = {2,5,8,  1,4,7,  3,6,9,12,  14,17,19,  13,16,18};
__constant__ int c_seg_e[NSEG] = {5,8,11, 4,7,10, 6,9,12,15, 17,19,21,  16,18,20};
__constant__ int c_path_off[NPATH] = {0,3,6,10,13};
__constant__ int c_path_cnt[NPATH] = {3,3,4,3,3};

// ---------------- packed f32x2 primitives (sm_103a) ----------------
typedef unsigned long long f2;

__device__ __forceinline__ f2 pk2(float lo, float hi) {
    f2 r; asm("mov.b64 %0, {%1, %2};" : "=l"(r) : "f"(lo), "f"(hi)); return r;
}
__device__ __forceinline__ void upk2(float& lo, float& hi, f2 v) {
    asm("mov.b64 {%0, %1}, %2;" : "=f"(lo), "=f"(hi) : "l"(v));
}
__device__ __forceinline__ f2 bc(float v) {
    unsigned u = __float_as_uint(v);
    return ((f2)u << 32) | (f2)u;
}
__device__ __forceinline__ f2 f2fma(f2 a, f2 b, f2 c) {
    f2 r; asm("fma.rn.f32x2 %0, %1, %2, %3;" : "=l"(r) : "l"(a), "l"(b), "l"(c)); return r;
}
__device__ __forceinline__ f2 f2mul(f2 a, f2 b) {
    f2 r; asm("mul.rn.f32x2 %0, %1, %2;" : "=l"(r) : "l"(a), "l"(b)); return r;
}
__device__ __forceinline__ f2 f2add(f2 a, f2 b) {
    f2 r; asm("add.rn.f32x2 %0, %1, %2;" : "=l"(r) : "l"(a), "l"(b)); return r;
}
__device__ __forceinline__ f2 f2sub(f2 a, f2 b) {
    f2 r; asm("sub.rn.f32x2 %0, %1, %2;" : "=l"(r) : "l"(a), "l"(b)); return r;
}
__device__ __forceinline__ f2 f2abs(f2 a) { return a & 0x7FFFFFFF7FFFFFFFULL; }

struct V3p { f2 x, y, z; };

__device__ __forceinline__ V3p p_sub(V3p a, V3p b) {
    return { f2sub(a.x,b.x), f2sub(a.y,b.y), f2sub(a.z,b.z) };
}
__device__ __forceinline__ V3p p_cross(V3p a, V3p b) {
    return { f2sub(f2mul(a.y, b.z), f2mul(a.z, b.y)),
             f2sub(f2mul(a.z, b.x), f2mul(a.x, b.z)),
             f2sub(f2mul(a.x, b.y), f2mul(a.y, b.x)) };
}
__device__ __forceinline__ f2 p_dot(V3p a, V3p b) {
    return f2fma(a.z, b.z, f2fma(a.y, b.y, f2mul(a.x, b.x)));
}

__device__ __forceinline__ f2 grsqrt2(f2 ss) {
    float l, h; upk2(l, h, ss);
    float rl = fminf(rsqrtf(l), 1e30f);
    float rh = fminf(rsqrtf(h), 1e30f);
    return pk2(rl, rh);
}

// A&S 4.4.46 packed asin: asin(a) = pi/2 - sqrt(1-a)*P7(a), a=|x| in [0,1],
// |eps|<=2e-8; saturates for |x|>1 (== clip+asin). No selects, no blends.
__device__ __forceinline__ f2 asin2(f2 x) {
    f2 ax = f2abs(x);
    f2 w  = f2sub(bc(1.0f), ax);
    float wl, wh; upk2(wl, wh, w);
    float sl = fmaxf(wl * rsqrtf(wl), 0.0f);   // sqrt(w); w<=0 -> 0
    float sh = fmaxf(wh * rsqrtf(wh), 0.0f);
    f2 s = pk2(sl, sh);
    f2 p = bc(-1.2624911e-3f);
    p = f2fma(p, ax, bc( 6.6700901e-3f));
    p = f2fma(p, ax, bc(-1.70881256e-2f));
    p = f2fma(p, ax, bc( 3.08918810e-2f));
    p = f2fma(p, ax, bc(-5.01743046e-2f));
    p = f2fma(p, ax, bc( 8.89789874e-2f));
    p = f2fma(p, ax, bc(-2.145988016e-1f));
    p = f2fma(p, ax, bc( 1.5707963050f));
    f2 r = f2sub(bc(1.5707963267948966f), f2mul(s, p));   // >= 0
    return r | (x & 0x8000000080000000ULL);                // apply sign(x)
}

__device__ __forceinline__ float wmaxf(float v) {
    #pragma unroll
    for (int o = 16; o; o >>= 1) v = fmaxf(v, __shfl_xor_sync(0xffffffffu, v, o));
    return v;
}
__device__ __forceinline__ float wminf(float v) {
    #pragma unroll
    for (int o = 16; o; o >>= 1) v = fminf(v, __shfl_xor_sync(0xffffffffu, v, o));
    return v;
}

// bbox-overlap flag for one global frame, straight from gmem (warp-collective)
__device__ __forceinline__ float flag_of_frame(
    const float* __restrict__ motion1, const float* __restrict__ motion2,
    int gf, int lane)
{
    const float* p1 = motion1 + (size_t)gf * 66;
    const float* p2 = motion2 + (size_t)gf * 66;
    bool ok = lane < JJ;
    float x1 = ok ? p1[3*lane]     :  1e30f;
    float z1 = ok ? p1[3*lane + 2] :  1e30f;
    float x2 = ok ? p2[3*lane]     :  1e30f;
    float z2 = ok ? p2[3*lane + 2] :  1e30f;
    float X1 = ok ? x1 : -1e30f, Z1 = ok ? z1 : -1e30f;
    float X2 = ok ? x2 : -1e30f, Z2 = ok ? z2 : -1e30f;
    float nx1 = wminf(x1), xx1 = wmaxf(X1);
    float nz1 = wminf(z1), xz1 = wmaxf(Z1);
    float nx2 = wminf(x2), xx2 = wmaxf(X2);
    float nz2 = wminf(z2), xz2 = wmaxf(Z2);
    bool fl = (xx1 >= nx2) && (xx2 >= nx1) && (xz1 >= nz2) && (xz2 >= nz1);
    return fl ? 1.0f : 0.0f;
}

// gbuf paired layout: f2 at [mlo*16+n] holds (lo = gli[mlo], hi = gli[mlo+8]).
// Scalar float index of (m, n) inside the f2 array viewed as floats:
__device__ __forceinline__ int gidx(int m, int n) {
    return (m < 8) ? ((m * 16 + n) << 1) : ((((m - 8) * 16 + n) << 1) | 1);
}

// Fused: CTA = 16 warps = 16 poses (frames f0..f0+15), 15 outputs (f0..f0+14).
__global__ void __launch_bounds__(NW * 32, 2) fused_kernel(
    const float* __restrict__ motion1,
    const float* __restrict__ motion2,
    float* __restrict__ out)
{
    const int w    = threadIdx.x >> 5;
    const int lane = threadIdx.x & 31;
    const int b    = blockIdx.x / CPR;
    const int c    = blockIdx.x % CPR;
    const int f0   = c * OPC;
    const int row  = b * FF;

    __shared__ float2 jnt[NW][2][33];
    __shared__ f2     pkj[NW][48];     // [mlo*6 + 0..2] = s1 packed, [3..5] = r12 packed
    __shared__ f2     gbuf[NW][128];   // paired gli: (mlo, mlo+8)
    __shared__ float  pose[NW][32];
    __shared__ float  flg[NW + 2];     // flags for frames f0-1 .. f0+16

    const float INV4PI = 0.07957747154594767f;

    const int  pf     = f0 + w;
    const bool pvalid = pf < FF;                       // only false for c=15,w=15
    const int  gf     = row + (pvalid ? pf : FF - 1);  // clamp (pose unused then)

    {   // stage joints (float2; element 32 by lane 0)
        const float2* p1 = (const float2*)motion1 + (size_t)gf * 33;
        const float2* p2 = (const float2*)motion2 + (size_t)gf * 33;
        jnt[w][0][lane] = p1[lane];
        jnt[w][1][lane] = p2[lane];
        if (lane == 0) { jnt[w][0][32] = p1[32]; jnt[w][1][32] = p2[32]; }
    }
    __syncwarp();

    const float* m1s = (const float*)jnt[w][0];
    const float* m2s = (const float*)jnt[w][1];

    // prepack m1: s1 (pt=0) and r12 = e1 - s1 (pt=1), paired (mlo, mlo+8)
    {
        #pragma unroll
        for (int l = lane; l < 48; l += 32) {
            int cc   = l % 3;
            int rest = l / 3;        // 0..15
            int pt   = rest & 1;
            int mlo  = rest >> 1;    // 0..7
            float slo = m1s[3*c_seg_s[mlo]     + cc];
            float shi = m1s[3*c_seg_s[mlo + 8] + cc];
            float vlo, vhi;
            if (pt) {
                vlo = m1s[3*c_seg_e[mlo]     + cc] - slo;   // r12 lo
                vhi = m1s[3*c_seg_e[mlo + 8] + cc] - shi;   // r12 hi
            } else {
                vlo = slo; vhi = shi;
            }
            pkj[w][l] = pk2(vlo, vhi);
        }
    }

    // bbox flag from staged smem -> slot w+1 (frame f0+w)
    {
        bool ok = lane < JJ;
        float x1 = ok ? m1s[3*lane]     :  1e30f;
        float z1 = ok ? m1s[3*lane + 2] :  1e30f;
        float x2 = ok ? m2s[3*lane]     :  1e30f;
        float z2 = ok ? m2s[3*lane + 2] :  1e30f;
        float X1 = ok ? x1 : -1e30f, Z1 = ok ? z1 : -1e30f;
        float X2 = ok ? x2 : -1e30f, Z2 = ok ? z2 : -1e30f;
        float nx1 = wminf(x1), xx1 = wmaxf(X1);
        float nz1 = wminf(z1), xz1 = wmaxf(Z1);
        float nx2 = wminf(x2), xx2 = wmaxf(X2);
        float nz2 = wminf(z2), xz2 = wmaxf(Z2);
        if (lane == 0) {
            bool fl = (xx1 >= nx2) && (xx2 >= nx1) && (xz1 >= nz2) && (xz2 >= nz1);
            flg[w + 1] = (fl && pvalid) ? 1.0f : 0.0f;
        }
    }

    // boundary flags: slot 0 = frame f0-1 (warp 0), slot 17 = frame f0+16 (warp 1)
    if (w == 0) {
        float v = (c > 0) ? flag_of_frame(motion1, motion2, row + f0 - 1, lane) : 0.0f;
        if (lane == 0) flg[0] = v;
    }
    if (w == 1) {
        int hf = f0 + NW;
        float v = (hf < FF) ? flag_of_frame(motion1, motion2, row + hf, lane) : 0.0f;
        if (lane == 0) flg[NW + 1] = v;
    }
    __syncwarp();

    // ---- packed GLI: lane covers n = lane&15; m pairs (2i+h, 2i+h+8) ----
    const int n = lane & 15;
    const int h = lane >> 4;
    const int js2 = 3 * c_seg_s[n], je2 = 3 * c_seg_e[n];
    const V3p s2p = { bc(m2s[js2]), bc(m2s[js2+1]), bc(m2s[js2+2]) };
    const V3p e2p = { bc(m2s[je2]), bc(m2s[je2+1]), bc(m2s[je2+2]) };
    const f2* pj = &pkj[w][0];

    #pragma unroll
    for (int i = 0; i < 4; ++i) {
        const int mlo = 2 * i + h;
        const int base = mlo * 6;
        V3p s1p = { pj[base+0], pj[base+1], pj[base+2] };   // LDS.64, broadcast
        V3p r12 = { pj[base+3], pj[base+4], pj[base+5] };   // prepacked e1-s1

        V3p r13 = p_sub(s2p, s1p);
        V3p r14 = p_sub(e2p, s1p);

        V3p A  = p_cross(r13, r14);
        V3p Bv = p_cross(r12, r14);
        V3p Cv = p_cross(r12, r13);

        f2 gAA = p_dot(A, A);
        f2 gBB = p_dot(Bv, Bv);
        f2 gCC = p_dot(Cv, Cv);
        f2 gAB = p_dot(A, Bv);
        f2 gBC = p_dot(Bv, Cv);
        f2 gCA = p_dot(Cv, A);

        f2 ss2 = f2add(f2add(gAA, gBB), gCC);
        ss2 = f2fma(gAB, bc(-2.0f), ss2);
        ss2 = f2fma(gBC, bc(-2.0f), ss2);
        ss2 = f2fma(gCA, bc( 2.0f), ss2);

        f2 n12 = f2sub(f2sub(gBB, gAB), gBC);
        f2 n23 = f2sub(f2sub(gBC, gCA), gCC);

        f2 r0 = grsqrt2(gAA);
        f2 r1 = grsqrt2(gBB);
        f2 r2 = grsqrt2(ss2);
        f2 r3 = grsqrt2(gCC);

        f2 d01 = f2mul(f2mul(gAB, r0), r1);
        f2 d12 = f2mul(f2mul(n12, r1), r2);
        f2 d23 = f2mul(f2mul(n23, r2), r3);
        f2 d30 = f2mul(f2mul(gCA, r3), r0);
        f2 tot = f2sub(f2add(asin2(d01), asin2(d12)),
                       f2add(asin2(d23), asin2(d30)));
        tot = f2mul(tot, bc(INV4PI));

        // ref sign = -B·r13; flip tot where sgB >= 0 (packed, branchless)
        f2 sgB = p_dot(Bv, r13);
        f2 mask = (~sgB) & 0x8000000080000000ULL;
        gbuf[w][mlo * 16 + n] = tot ^ mask;     // STS.64: (gli[mlo], gli[mlo+8])
    }
    __syncwarp();

    if (lane < 25) {
        const float* gv = (const float*)gbuf[w];
        const int pi = lane / 5;
        const int pj2 = lane % 5;
        const int mo = c_path_off[pi], mc = c_path_cnt[pi];
        const int no = c_path_off[pj2], nc = c_path_cnt[pj2];
        float s = 0.0f;
        for (int m = mo; m < mo + mc; ++m)
            for (int nn = no; nn < no + nc; ++nn)
                s += gv[gidx(m, nn)];
        pose[w][lane] = s;
    }

    __syncthreads();

    // ---- velocity output: warp w -> f = f0 + w (needs pose[w], pose[w+1]) ----
    const int f = f0 + w;
    if (w < OPC && f < FF - 1) {
        float m0 = (flg[w]   != 0.0f || flg[w+1] != 0.0f || flg[w+2] != 0.0f) ? 1.0f : 0.0f;
        float m1 = (flg[w+1] != 0.0f || flg[w+2] != 0.0f || flg[w+3] != 0.0f) ? 1.0f : 0.0f;
        float d = 0.0f;
        if (lane < 25) {
            d = fabsf(pose[w + 1][lane] * m1 - pose[w][lane] * m0);
        }
        d = wmaxf(d);
        if (lane == 0) out[b * (FF - 1) + f] = d;
    }
}

extern "C" void kernel_launch(void* const* d_in, const int* in_sizes, int n_in,
                              void* d_out, int out_size)
{
    const float* motion1 = (const float*)d_in[0];
    const float* motion2 = (const float*)d_in[1];
    float* out = (float*)d_out;

    fused_kernel<<<BB * CPR, NW * 32>>>(motion1, motion2, out);
}

// round 16
// speedup vs baseline: 1.3773x; 1.0010x over previous
#include <cuda_runtime.h>
#include <math.h>

#define BB 64
#define FF 240
#define JJ 22
#define NSEG 16
#define NPATH 5
#define NW 16            // warps per CTA = poses per CTA; outputs per CTA = 15
#define OPC 15           // outputs per chunk
#define CPR 16           // chunks per row

__constant__ int c_seg_s[NSEG] = {2,5,8,  1,4,7,  3,6,9,12,  14,17,19,  13,16,18};
__constant__ int c_seg_e[NSEG] = {5,8,11, 4,7,10, 6,9,12,15, 17,19,21,  16,18,20};
__constant__ int c_path_off[NPATH] = {0,3,6,10,13};
__constant__ int c_path_cnt[NPATH] = {3,3,4,3,3};

// ---------------- packed f32x2 primitives (sm_103a) ----------------
typedef unsigned long long f2;

__device__ __forceinline__ f2 pk2(float lo, float hi) {
    f2 r; asm("mov.b64 %0, {%1, %2};" : "=l"(r) : "f"(lo), "f"(hi)); return r;
}
__device__ __forceinline__ void upk2(float& lo, float& hi, f2 v) {
    asm("mov.b64 {%0, %1}, %2;" : "=f"(lo), "=f"(hi) : "l"(v));
}
__device__ __forceinline__ f2 bc(float v) {
    unsigned u = __float_as_uint(v);
    return ((f2)u << 32) | (f2)u;
}
__device__ __forceinline__ f2 f2fma(f2 a, f2 b, f2 c) {
    f2 r; asm("fma.rn.f32x2 %0, %1, %2, %3;" : "=l"(r) : "l"(a), "l"(b), "l"(c)); return r;
}
__device__ __forceinline__ f2 f2mul(f2 a, f2 b) {
    f2 r; asm("mul.rn.f32x2 %0, %1, %2;" : "=l"(r) : "l"(a), "l"(b)); return r;
}
__device__ __forceinline__ f2 f2add(f2 a, f2 b) {
    f2 r; asm("add.rn.f32x2 %0, %1, %2;" : "=l"(r) : "l"(a), "l"(b)); return r;
}
__device__ __forceinline__ f2 f2sub(f2 a, f2 b) {
    f2 r; asm("sub.rn.f32x2 %0, %1, %2;" : "=l"(r) : "l"(a), "l"(b)); return r;
}
__device__ __forceinline__ f2 f2abs(f2 a) { return a & 0x7FFFFFFF7FFFFFFFULL; }

__device__ __forceinline__ float sqrt_approx(float x) {
    float r; asm("sqrt.approx.f32 %0, %1;" : "=f"(r) : "f"(x)); return r;
}

struct V3p { f2 x, y, z; };

__device__ __forceinline__ V3p p_sub(V3p a, V3p b) {
    return { f2sub(a.x,b.x), f2sub(a.y,b.y), f2sub(a.z,b.z) };
}
__device__ __forceinline__ V3p p_cross(V3p a, V3p b) {
    return { f2sub(f2mul(a.y, b.z), f2mul(a.z, b.y)),
             f2sub(f2mul(a.z, b.x), f2mul(a.x, b.z)),
             f2sub(f2mul(a.x, b.y), f2mul(a.y, b.x)) };
}
__device__ __forceinline__ f2 p_dot(V3p a, V3p b) {
    return f2fma(a.z, b.z, f2fma(a.y, b.y, f2mul(a.x, b.x)));
}

// guarded packed reciprocal-sqrt: ss==0 -> 1e30 (inf-min); ss<0 (rounding) ->
// rsqrt=NaN -> fminf(NaN,1e30)=1e30 -> downstream d saturates in asin (=clip).
__device__ __forceinline__ f2 grsqrt2(f2 ss) {
    float l, h; upk2(l, h, ss);
    float rl = fminf(rsqrtf(l), 1e30f);
    float rh = fminf(rsqrtf(h), 1e30f);
    return pk2(rl, rh);
}

// A&S 4.4.46 packed asin PRE-SCALED by 1/(4*pi):
//   asin(a)/(4pi) = 0.125 - sqrt(1-a) * P7(a),  a=|x| in [0,1]
// Saturates for |x|>1 (1-a<0 -> NaN -> 0 -> 0.125) == clip+asin. Sign via OR.
__device__ __forceinline__ f2 asin2s(f2 x) {
    f2 ax = f2abs(x);
    f2 w  = f2sub(bc(1.0f), ax);
    float wl, wh; upk2(wl, wh, w);
    float sl = fmaxf(sqrt_approx(wl), 0.0f);   // sqrt(w); w<=0 -> 0
    float sh = fmaxf(sqrt_approx(wh), 0.0f);
    f2 s = pk2(sl, sh);
    f2 p = bc(-1.004659e-4f);                  // coeffs = A&S * (1/4pi)
    p = f2fma(p, ax, bc( 5.30789e-4f));
    p = f2fma(p, ax, bc(-1.35983e-3f));
    p = f2fma(p, ax, bc( 2.45830e-3f));
    p = f2fma(p, ax, bc(-3.99274e-3f));
    p = f2fma(p, ax, bc( 7.08072e-3f));
    p = f2fma(p, ax, bc(-1.7077312e-2f));
    p = f2fma(p, ax, bc( 1.2499999827e-1f));
    f2 r = f2sub(bc(0.125f), f2mul(s, p));     // >= 0, max 0.125 = (pi/2)/(4pi)
    return r | (x & 0x8000000080000000ULL);    // apply sign(x)
}

__device__ __forceinline__ float wmaxf(float v) {
    #pragma unroll
    for (int o = 16; o; o >>= 1) v = fmaxf(v, __shfl_xor_sync(0xffffffffu, v, o));
    return v;
}
__device__ __forceinline__ float wminf(float v) {
    #pragma unroll
    for (int o = 16; o; o >>= 1) v = fminf(v, __shfl_xor_sync(0xffffffffu, v, o));
    return v;
}

// bbox-overlap flag for one global frame, straight from gmem (warp-collective)
__device__ __forceinline__ float flag_of_frame(
    const float* __restrict__ motion1, const float* __restrict__ motion2,
    int gf, int lane)
{
    const float* p1 = motion1 + (size_t)gf * 66;
    const float* p2 = motion2 + (size_t)gf * 66;
    bool ok = lane < JJ;
    float x1 = ok ? p1[3*lane]     :  1e30f;
    float z1 = ok ? p1[3*lane + 2] :  1e30f;
    float x2 = ok ? p2[3*lane]     :  1e30f;
    float z2 = ok ? p2[3*lane + 2] :  1e30f;
    float X1 = ok ? x1 : -1e30f, Z1 = ok ? z1 : -1e30f;
    float X2 = ok ? x2 : -1e30f, Z2 = ok ? z2 : -1e30f;
    float nx1 = wminf(x1), xx1 = wmaxf(X1);
    float nz1 = wminf(z1), xz1 = wmaxf(Z1);
    float nx2 = wminf(x2), xx2 = wmaxf(X2);
    float nz2 = wminf(z2), xz2 = wmaxf(Z2);
    bool fl = (xx1 >= nx2) && (xx2 >= nx1) && (xz1 >= nz2) && (xz2 >= nz1);
    return fl ? 1.0f : 0.0f;
}

// gbuf paired layout: f2 at [mlo*16+n] holds (lo = gli[mlo], hi = gli[mlo+8]).
__device__ __forceinline__ int gidx(int m, int n) {
    return (m < 8) ? ((m * 16 + n) << 1) : ((((m - 8) * 16 + n) << 1) | 1);
}

// Fused: CTA = 16 warps = 16 poses (frames f0..f0+15), 15 outputs (f0..f0+14).
__global__ void __launch_bounds__(NW * 32, 2) fused_kernel(
    const float* __restrict__ motion1,
    const float* __restrict__ motion2,
    float* __restrict__ out)
{
    const int w    = threadIdx.x >> 5;
    const int lane = threadIdx.x & 31;
    const int b    = blockIdx.x / CPR;
    const int c    = blockIdx.x % CPR;
    const int f0   = c * OPC;
    const int row  = b * FF;

    __shared__ float2 jnt[NW][2][33];
    __shared__ __align__(16) f2 pkj[NW][48];  // [mlo*6+0..2]=s1, [3..5]=r12 (packed mlo,mlo+8)
    __shared__ f2     gbuf[NW][128];          // paired gli: (mlo, mlo+8)
    __shared__ float  pose[NW][32];
    __shared__ float  flg[NW + 2];            // flags for frames f0-1 .. f0+16

    const int  pf     = f0 + w;
    const bool pvalid = pf < FF;                       // only false for c=15,w=15
    const int  gf     = row + (pvalid ? pf : FF - 1);  // clamp (pose unused then)

    {   // stage joints (float2; element 32 by lane 0)
        const float2* p1 = (const float2*)motion1 + (size_t)gf * 33;
        const float2* p2 = (const float2*)motion2 + (size_t)gf * 33;
        jnt[w][0][lane] = p1[lane];
        jnt[w][1][lane] = p2[lane];
        if (lane == 0) { jnt[w][0][32] = p1[32]; jnt[w][1][32] = p2[32]; }
    }
    __syncwarp();

    const float* m1s = (const float*)jnt[w][0];
    const float* m2s = (const float*)jnt[w][1];

    // prepack m1: s1 (pt=0) and r12 = e1 - s1 (pt=1), paired (mlo, mlo+8)
    {
        #pragma unroll
        for (int l = lane; l < 48; l += 32) {
            int cc   = l % 3;
            int rest = l / 3;        // 0..15
            int pt   = rest & 1;
            int mlo  = rest >> 1;    // 0..7
            float slo = m1s[3*c_seg_s[mlo]     + cc];
            float shi = m1s[3*c_seg_s[mlo + 8] + cc];
            float vlo, vhi;
            if (pt) {
                vlo = m1s[3*c_seg_e[mlo]     + cc] - slo;   // r12 lo
                vhi = m1s[3*c_seg_e[mlo + 8] + cc] - shi;   // r12 hi
            } else {
                vlo = slo; vhi = shi;
            }
            pkj[w][l] = pk2(vlo, vhi);
        }
    }

    // bbox flag from staged smem -> slot w+1 (frame f0+w)
    {
        bool ok = lane < JJ;
        float x1 = ok ? m1s[3*lane]     :  1e30f;
        float z1 = ok ? m1s[3*lane + 2] :  1e30f;
        float x2 = ok ? m2s[3*lane]     :  1e30f;
        float z2 = ok ? m2s[3*lane + 2] :  1e30f;
        float X1 = ok ? x1 : -1e30f, Z1 = ok ? z1 : -1e30f;
        float X2 = ok ? x2 : -1e30f, Z2 = ok ? z2 : -1e30f;
        float nx1 = wminf(x1), xx1 = wmaxf(X1);
        float nz1 = wminf(z1), xz1 = wmaxf(Z1);
        float nx2 = wminf(x2), xx2 = wmaxf(X2);
        float nz2 = wminf(z2), xz2 = wmaxf(Z2);
        if (lane == 0) {
            bool fl = (xx1 >= nx2) && (xx2 >= nx1) && (xz1 >= nz2) && (xz2 >= nz1);
            flg[w + 1] = (fl && pvalid) ? 1.0f : 0.0f;
        }
    }

    // boundary flags: slot 0 = frame f0-1 (warp 0), slot 17 = frame f0+16 (warp 1)
    if (w == 0) {
        float v = (c > 0) ? flag_of_frame(motion1, motion2, row + f0 - 1, lane) : 0.0f;
        if (lane == 0) flg[0] = v;
    }
    if (w == 1) {
        int hf = f0 + NW;
        float v = (hf < FF) ? flag_of_frame(motion1, motion2, row + hf, lane) : 0.0f;
        if (lane == 0) flg[NW + 1] = v;
    }
    __syncwarp();

    // ---- packed GLI: lane covers n = lane&15; m pairs (2i+h, 2i+h+8) ----
    const int n = lane & 15;
    const int h = lane >> 4;
    const int js2 = 3 * c_seg_s[n], je2 = 3 * c_seg_e[n];
    const V3p s2p = { bc(m2s[js2]), bc(m2s[js2+1]), bc(m2s[js2+2]) };
    const V3p e2p = { bc(m2s[je2]), bc(m2s[je2+1]), bc(m2s[je2+2]) };
    const ulonglong2* pj2 = (const ulonglong2*)&pkj[w][0];

    #pragma unroll
    for (int i = 0; i < 4; ++i) {
        const int mlo = 2 * i + h;
        // 3x LDS.128 (broadcast): (s1.x,s1.y), (s1.z,r12.x), (r12.y,r12.z)
        ulonglong2 q0 = pj2[mlo * 3 + 0];
        ulonglong2 q1 = pj2[mlo * 3 + 1];
        ulonglong2 q2 = pj2[mlo * 3 + 2];
        V3p s1p = { q0.x, q0.y, q1.x };
        V3p r12 = { q1.y, q2.x, q2.y };

        V3p r13 = p_sub(s2p, s1p);
        V3p r14 = p_sub(e2p, s1p);

        V3p A  = p_cross(r13, r14);
        V3p Bv = p_cross(r12, r14);
        V3p Cv = p_cross(r12, r13);

        f2 gAA = p_dot(A, A);
        f2 gBB = p_dot(Bv, Bv);
        f2 gCC = p_dot(Cv, Cv);
        f2 gAB = p_dot(A, Bv);
        f2 gBC = p_dot(Bv, Cv);
        f2 gCA = p_dot(Cv, A);

        f2 ss2 = f2add(f2add(gAA, gBB), gCC);
        ss2 = f2fma(gAB, bc(-2.0f), ss2);
        ss2 = f2fma(gBC, bc(-2.0f), ss2);
        ss2 = f2fma(gCA, bc( 2.0f), ss2);

        f2 n12 = f2sub(f2sub(gBB, gAB), gBC);
        f2 n23 = f2sub(f2sub(gBC, gCA), gCC);

        f2 r0 = grsqrt2(gAA);
        f2 r1 = grsqrt2(gBB);
        f2 r2 = grsqrt2(ss2);
        f2 r3 = grsqrt2(gCC);

        f2 d01 = f2mul(f2mul(gAB, r0), r1);
        f2 d12 = f2mul(f2mul(n12, r1), r2);
        f2 d23 = f2mul(f2mul(n23, r2), r3);
        f2 d30 = f2mul(f2mul(gCA, r3), r0);
        // asin pre-scaled by 1/(4pi); no post-multiply needed
        f2 tot = f2sub(f2add(asin2s(d01), asin2s(d12)),
                       f2add(asin2s(d23), asin2s(d30)));

        // ref sign = -B·r13; flip tot where sgB >= 0 (packed, branchless)
        f2 sgB = p_dot(Bv, r13);
        f2 mask = (~sgB) & 0x8000000080000000ULL;
        gbuf[w][mlo * 16 + n] = tot ^ mask;     // STS.64: (gli[mlo], gli[mlo+8])
    }
    __syncwarp();

    if (lane < 25) {
        const float* gv = (const float*)gbuf[w];
        const int pi = lane / 5;
        const int pjx = lane % 5;
        const int mo = c_path_off[pi], mc = c_path_cnt[pi];
        const int no = c_path_off[pjx], nc = c_path_cnt[pjx];
        float s = 0.0f;
        for (int m = mo; m < mo + mc; ++m)
            for (int nn = no; nn < no + nc; ++nn)
                s += gv[gidx(m, nn)];
        pose[w][lane] = s;
    }

    __syncthreads();

    // ---- velocity output: warp w -> f = f0 + w (needs pose[w], pose[w+1]) ----
    const int f = f0 + w;
    if (w < OPC && f < FF - 1) {
        float m0 = (flg[w]   != 0.0f || flg[w+1] != 0.0f || flg[w+2] != 0.0f) ? 1.0f : 0.0f;
        float m1 = (flg[w+1] != 0.0f || flg[w+2] != 0.0f || flg[w+3] != 0.0f) ? 1.0f : 0.0f;
        float d = 0.0f;
        if (lane < 25) {
            d = fabsf(pose[w + 1][lane] * m1 - pose[w][lane] * m0);
        }
        d = wmaxf(d);
        if (lane == 0) out[b * (FF - 1) + f] = d;
    }
}

extern "C" void kernel_launch(void* const* d_in, const int* in_sizes, int n_in,
                              void* d_out, int out_size)
{
    const float* motion1 = (const float*)d_in[0];
    const float* motion2 = (const float*)d_in[1];
    float* out = (float*)d_out;

    fused_kernel<<<BB * CPR, NW * 32>>>(motion1, motion2, out);
}

// round 17
// speedup vs baseline: 1.4662x; 1.0645x over previous
#include <cuda_runtime.h>
#include <math.h>

#define BB 64
#define FF 240
#define JJ 22
#define NSEG 16
#define NPATH 5
#define NP 16            // poses per CTA
#define NWARP 8          // warps per CTA; each warp owns 2 poses
#define OPC 15           // outputs per chunk
#define CPR 16           // chunks per row

__constant__ int c_seg_s[NSEG] = {2,5,8,  1,4,7,  3,6,9,12,  14,17,19,  13,16,18};
__constant__ int c_seg_e[NSEG] = {5,8,11, 4,7,10, 6,9,12,15, 17,19,21,  16,18,20};
__constant__ int c_path_off[NPATH] = {0,3,6,10,13};
__constant__ int c_path_cnt[NPATH] = {3,3,4,3,3};

// ---------------- packed f32x2 primitives (sm_103a) ----------------
typedef unsigned long long f2;

__device__ __forceinline__ f2 pk2(float lo, float hi) {
    f2 r; asm("mov.b64 %0, {%1, %2};" : "=l"(r) : "f"(lo), "f"(hi)); return r;
}
__device__ __forceinline__ void upk2(float& lo, float& hi, f2 v) {
    asm("mov.b64 {%0, %1}, %2;" : "=f"(lo), "=f"(hi) : "l"(v));
}
__device__ __forceinline__ f2 bc(float v) {
    unsigned u = __float_as_uint(v);
    return ((f2)u << 32) | (f2)u;
}
__device__ __forceinline__ f2 f2fma(f2 a, f2 b, f2 c) {
    f2 r; asm("fma.rn.f32x2 %0, %1, %2, %3;" : "=l"(r) : "l"(a), "l"(b), "l"(c)); return r;
}
__device__ __forceinline__ f2 f2mul(f2 a, f2 b) {
    f2 r; asm("mul.rn.f32x2 %0, %1, %2;" : "=l"(r) : "l"(a), "l"(b)); return r;
}
__device__ __forceinline__ f2 f2add(f2 a, f2 b) {
    f2 r; asm("add.rn.f32x2 %0, %1, %2;" : "=l"(r) : "l"(a), "l"(b)); return r;
}
__device__ __forceinline__ f2 f2sub(f2 a, f2 b) {
    f2 r; asm("sub.rn.f32x2 %0, %1, %2;" : "=l"(r) : "l"(a), "l"(b)); return r;
}
__device__ __forceinline__ f2 f2abs(f2 a) { return a & 0x7FFFFFFF7FFFFFFFULL; }

__device__ __forceinline__ float sqrt_approx(float x) {
    float r; asm("sqrt.approx.f32 %0, %1;" : "=f"(r) : "f"(x)); return r;
}

struct V3p { f2 x, y, z; };

__device__ __forceinline__ V3p p_sub(V3p a, V3p b) {
    return { f2sub(a.x,b.x), f2sub(a.y,b.y), f2sub(a.z,b.z) };
}
__device__ __forceinline__ V3p p_cross(V3p a, V3p b) {
    return { f2sub(f2mul(a.y, b.z), f2mul(a.z, b.y)),
             f2sub(f2mul(a.z, b.x), f2mul(a.x, b.z)),
             f2sub(f2mul(a.x, b.y), f2mul(a.y, b.x)) };
}
__device__ __forceinline__ f2 p_dot(V3p a, V3p b) {
    return f2fma(a.z, b.z, f2fma(a.y, b.y, f2mul(a.x, b.x)));
}

// guarded packed reciprocal-sqrt: ss==0 -> 1e30; ss<0 (rounding) -> NaN ->
// fminf(NaN,1e30)=1e30 -> downstream d saturates in asin (== clip semantics).
__device__ __forceinline__ f2 grsqrt2(f2 ss) {
    float l, h; upk2(l, h, ss);
    float rl = fminf(rsqrtf(l), 1e30f);
    float rh = fminf(rsqrtf(h), 1e30f);
    return pk2(rl, rh);
}

// A&S 4.4.46 packed asin PRE-SCALED by 1/(4*pi):
//   asin(a)/(4pi) = 0.125 - sqrt(1-a) * P7(a),  a=|x| in [0,1]
// Saturates for |x|>1 (1-a<0 -> NaN -> 0 -> 0.125) == clip+asin. Sign via OR.
__device__ __forceinline__ f2 asin2s(f2 x) {
    f2 ax = f2abs(x);
    f2 w  = f2sub(bc(1.0f), ax);
    float wl, wh; upk2(wl, wh, w);
    float sl = fmaxf(sqrt_approx(wl), 0.0f);
    float sh = fmaxf(sqrt_approx(wh), 0.0f);
    f2 s = pk2(sl, sh);
    f2 p = bc(-1.004659e-4f);                  // coeffs = A&S * (1/4pi)
    p = f2fma(p, ax, bc( 5.30789e-4f));
    p = f2fma(p, ax, bc(-1.35983e-3f));
    p = f2fma(p, ax, bc( 2.45830e-3f));
    p = f2fma(p, ax, bc(-3.99274e-3f));
    p = f2fma(p, ax, bc( 7.08072e-3f));
    p = f2fma(p, ax, bc(-1.7077312e-2f));
    p = f2fma(p, ax, bc( 1.2499999827e-1f));
    f2 r = f2sub(bc(0.125f), f2mul(s, p));     // >= 0
    return r | (x & 0x8000000080000000ULL);    // apply sign(x)
}

__device__ __forceinline__ float wmaxf(float v) {
    #pragma unroll
    for (int o = 16; o; o >>= 1) v = fmaxf(v, __shfl_xor_sync(0xffffffffu, v, o));
    return v;
}
__device__ __forceinline__ float wminf(float v) {
    #pragma unroll
    for (int o = 16; o; o >>= 1) v = fminf(v, __shfl_xor_sync(0xffffffffu, v, o));
    return v;
}

// bbox-overlap flag for one global frame, straight from gmem (warp-collective)
__device__ __forceinline__ float flag_of_frame(
    const float* __restrict__ motion1, const float* __restrict__ motion2,
    int gf, int lane)
{
    const float* p1 = motion1 + (size_t)gf * 66;
    const float* p2 = motion2 + (size_t)gf * 66;
    bool ok = lane < JJ;
    float x1 = ok ? p1[3*lane]     :  1e30f;
    float z1 = ok ? p1[3*lane + 2] :  1e30f;
    float x2 = ok ? p2[3*lane]     :  1e30f;
    float z2 = ok ? p2[3*lane + 2] :  1e30f;
    float X1 = ok ? x1 : -1e30f, Z1 = ok ? z1 : -1e30f;
    float X2 = ok ? x2 : -1e30f, Z2 = ok ? z2 : -1e30f;
    float nx1 = wminf(x1), xx1 = wmaxf(X1);
    float nz1 = wminf(z1), xz1 = wmaxf(Z1);
    float nx2 = wminf(x2), xx2 = wmaxf(X2);
    float nz2 = wminf(z2), xz2 = wmaxf(Z2);
    bool fl = (xx1 >= nx2) && (xx2 >= nx1) && (xz1 >= nz2) && (xz2 >= nz1);
    return fl ? 1.0f : 0.0f;
}

// gbuf paired layout: f2 at [mlo*16+n] holds (lo = gli[mlo], hi = gli[mlo+8]).
__device__ __forceinline__ int gidx(int m, int n) {
    return (m < 8) ? ((m * 16 + n) << 1) : ((((m - 8) * 16 + n) << 1) | 1);
}

// Fused: CTA = 8 warps x 2 poses = 16 poses (frames f0..f0+15), 15 outputs.
// 2 independent GLI streams per warp -> 2x ILP at the same occupancy.
__global__ void __launch_bounds__(NWARP * 32, 4) fused_kernel(
    const float* __restrict__ motion1,
    const float* __restrict__ motion2,
    float* __restrict__ out)
{
    const int wp   = threadIdx.x >> 5;            // warp 0..7
    const int lane = threadIdx.x & 31;
    const int b    = blockIdx.x / CPR;
    const int c    = blockIdx.x % CPR;
    const int f0   = c * OPC;
    const int row  = b * FF;

    __shared__ float2 jnt[NP][2][33];
    __shared__ __align__(16) f2 pkj[NP][48];  // [mlo*6+0..2]=s1, [3..5]=r12 (paired mlo,mlo+8)
    __shared__ f2     gbuf[NP][128];          // paired gli: (mlo, mlo+8)
    __shared__ float  pose[NP][32];
    __shared__ float  flg[NP + 2];            // flags for frames f0-1 .. f0+16

    const int n = lane & 15;
    const int h = lane >> 4;

    // ---- phase 1: stage + prepack + flag for both poses of this warp ----
    #pragma unroll
    for (int s = 0; s < 2; ++s) {
        const int  p      = 2 * wp + s;                    // pose slot 0..15
        const int  pf     = f0 + p;
        const bool pvalid = pf < FF;                       // false only c=15,p=15
        const int  gf     = row + (pvalid ? pf : FF - 1);  // clamp

        const float2* g1 = (const float2*)motion1 + (size_t)gf * 33;
        const float2* g2 = (const float2*)motion2 + (size_t)gf * 33;
        jnt[p][0][lane] = g1[lane];
        jnt[p][1][lane] = g2[lane];
        if (lane == 0) { jnt[p][0][32] = g1[32]; jnt[p][1][32] = g2[32]; }
        __syncwarp();

        const float* m1s = (const float*)jnt[p][0];
        const float* m2s = (const float*)jnt[p][1];

        // prepack m1: s1 (pt=0) and r12 = e1 - s1 (pt=1), paired (mlo, mlo+8)
        #pragma unroll
        for (int l = lane; l < 48; l += 32) {
            int cc   = l % 3;
            int rest = l / 3;
            int pt   = rest & 1;
            int mlo  = rest >> 1;
            float slo = m1s[3*c_seg_s[mlo]     + cc];
            float shi = m1s[3*c_seg_s[mlo + 8] + cc];
            float vlo, vhi;
            if (pt) {
                vlo = m1s[3*c_seg_e[mlo]     + cc] - slo;
                vhi = m1s[3*c_seg_e[mlo + 8] + cc] - shi;
            } else {
                vlo = slo; vhi = shi;
            }
            pkj[p][l] = pk2(vlo, vhi);
        }

        // bbox flag -> slot p+1
        {
            bool ok = lane < JJ;
            float x1 = ok ? m1s[3*lane]     :  1e30f;
            float z1 = ok ? m1s[3*lane + 2] :  1e30f;
            float x2 = ok ? m2s[3*lane]     :  1e30f;
            float z2 = ok ? m2s[3*lane + 2] :  1e30f;
            float X1 = ok ? x1 : -1e30f, Z1 = ok ? z1 : -1e30f;
            float X2 = ok ? x2 : -1e30f, Z2 = ok ? z2 : -1e30f;
            float nx1 = wminf(x1), xx1 = wmaxf(X1);
            float nz1 = wminf(z1), xz1 = wmaxf(Z1);
            float nx2 = wminf(x2), xx2 = wmaxf(X2);
            float nz2 = wminf(z2), xz2 = wmaxf(Z2);
            if (lane == 0) {
                bool fl = (xx1 >= nx2) && (xx2 >= nx1) && (xz1 >= nz2) && (xz2 >= nz1);
                flg[p + 1] = (fl && pvalid) ? 1.0f : 0.0f;
            }
        }
    }

    // boundary flags: slot 0 = frame f0-1 (warp 0), slot 17 = frame f0+16 (warp 1)
    if (wp == 0) {
        float v = (c > 0) ? flag_of_frame(motion1, motion2, row + f0 - 1, lane) : 0.0f;
        if (lane == 0) flg[0] = v;
    }
    if (wp == 1) {
        int hf = f0 + NP;
        float v = (hf < FF) ? flag_of_frame(motion1, motion2, row + hf, lane) : 0.0f;
        if (lane == 0) flg[NP + 1] = v;
    }
    __syncwarp();

    // ---- phase 2: GLI for both poses; two independent streams, unrolled ----
    #pragma unroll
    for (int s = 0; s < 2; ++s) {
        const int p = 2 * wp + s;
        const float* m2s = (const float*)jnt[p][1];
        const int js2 = 3 * c_seg_s[n], je2 = 3 * c_seg_e[n];
        const V3p s2p = { bc(m2s[js2]), bc(m2s[js2+1]), bc(m2s[js2+2]) };
        const V3p e2p = { bc(m2s[je2]), bc(m2s[je2+1]), bc(m2s[je2+2]) };
        const ulonglong2* pj2 = (const ulonglong2*)&pkj[p][0];

        #pragma unroll
        for (int i = 0; i < 4; ++i) {
            const int mlo = 2 * i + h;
            ulonglong2 q0 = pj2[mlo * 3 + 0];
            ulonglong2 q1 = pj2[mlo * 3 + 1];
            ulonglong2 q2 = pj2[mlo * 3 + 2];
            V3p s1p = { q0.x, q0.y, q1.x };
            V3p r12 = { q1.y, q2.x, q2.y };

            V3p r13 = p_sub(s2p, s1p);
            V3p r14 = p_sub(e2p, s1p);

            V3p A  = p_cross(r13, r14);
            V3p Bv = p_cross(r12, r14);
            V3p Cv = p_cross(r12, r13);

            f2 gAA = p_dot(A, A);
            f2 gBB = p_dot(Bv, Bv);
            f2 gCC = p_dot(Cv, Cv);
            f2 gAB = p_dot(A, Bv);
            f2 gBC = p_dot(Bv, Cv);
            f2 gCA = p_dot(Cv, A);

            f2 ss2 = f2add(f2add(gAA, gBB), gCC);
            ss2 = f2fma(gAB, bc(-2.0f), ss2);
            ss2 = f2fma(gBC, bc(-2.0f), ss2);
            ss2 = f2fma(gCA, bc( 2.0f), ss2);

            f2 n12 = f2sub(f2sub(gBB, gAB), gBC);
            f2 n23 = f2sub(f2sub(gBC, gCA), gCC);

            f2 r0 = grsqrt2(gAA);
            f2 r1 = grsqrt2(gBB);
            f2 r2 = grsqrt2(ss2);
            f2 r3 = grsqrt2(gCC);

            f2 d01 = f2mul(f2mul(gAB, r0), r1);
            f2 d12 = f2mul(f2mul(n12, r1), r2);
            f2 d23 = f2mul(f2mul(n23, r2), r3);
            f2 d30 = f2mul(f2mul(gCA, r3), r0);
            f2 tot = f2sub(f2add(asin2s(d01), asin2s(d12)),
                           f2add(asin2s(d23), asin2s(d30)));

            // ref sign = -B·r13; flip tot where (B·r13) >= +0 (packed, branchless)
            f2 sgB = p_dot(Bv, r13);
            f2 mask = (~sgB) & 0x8000000080000000ULL;
            gbuf[p][mlo * 16 + n] = tot ^ mask;   // STS.64: (gli[mlo], gli[mlo+8])
        }
        __syncwarp();

        if (lane < 25) {
            const float* gv = (const float*)gbuf[p];
            const int pi = lane / 5;
            const int pjx = lane % 5;
            const int mo = c_path_off[pi], mc = c_path_cnt[pi];
            const int no = c_path_off[pjx], nc = c_path_cnt[pjx];
            float sum = 0.0f;
            for (int m = mo; m < mo + mc; ++m)
                for (int nn = no; nn < no + nc; ++nn)
                    sum += gv[gidx(m, nn)];
            pose[p][lane] = sum;
        }
    }

    __syncthreads();

    // ---- phase 3: velocity outputs; warp wp emits outputs 2wp and 2wp+1 ----
    #pragma unroll
    for (int s = 0; s < 2; ++s) {
        const int o = 2 * wp + s;                 // output slot 0..15 (15 invalid)
        const int f = f0 + o;
        if (o < OPC && f < FF - 1) {
            float m0 = (flg[o]   != 0.0f || flg[o+1] != 0.0f || flg[o+2] != 0.0f) ? 1.0f : 0.0f;
            float m1 = (flg[o+1] != 0.0f || flg[o+2] != 0.0f || flg[o+3] != 0.0f) ? 1.0f : 0.0f;
            float d = 0.0f;
            if (lane < 25) {
                d = fabsf(pose[o + 1][lane] * m1 - pose[o][lane] * m0);
            }
            d = wmaxf(d);
            if (lane == 0) out[b * (FF - 1) + f] = d;
        }
    }
}

extern "C" void kernel_launch(void* const* d_in, const int* in_sizes, int n_in,
                              void* d_out, int out_size)
{
    const float* motion1 = (const float*)d_in[0];
    const float* motion2 = (const float*)d_in[1];
    float* out = (float*)d_out;

    fused_kernel<<<BB * CPR, NWARP * 32>>>(motion1, motion2, out);
}